// round 3
// baseline (speedup 1.0000x reference)
#include <cuda_runtime.h>

#define N_MAX 100000
#define E_MAX 1700000

// ---------------- static device scratch (referenced directly in kernels) -----
__device__ __align__(16) float g_t[(size_t)N_MAX * 64];  // GEMM out / prop in
__device__ __align__(16) float g_h[(size_t)N_MAX * 64];  // prop out / GEMM in
__device__ int   g_src[E_MAX];               // CSR: source node per edge (by dst)
__device__ float g_w[E_MAX];                 // CSR: norm weight per edge
__device__ int   g_deg[N_MAX];               // in-degree (incl self loop)
__device__ int   g_cur[N_MAX];               // scatter cursors
__device__ int   g_off[N_MAX + 1];           // CSR row offsets (by dst)
__device__ float g_dinv[N_MAX];              // deg^-1/2
__device__ int   g_bsums[256];               // scan block sums

// ---------------- graph preprocessing ----------------
__global__ void k_init(int n) {
    int i = blockIdx.x * blockDim.x + threadIdx.x;
    if (i < n) { g_deg[i] = 1; g_cur[i] = 0; }   // deg starts at 1: self loop
}

// NOTE: edge_index is int32 (JAX x64 disabled downcasts jnp.int64 -> int32)
__global__ void k_count(const int* __restrict__ ei, int E) {
    int e = blockIdx.x * blockDim.x + threadIdx.x;
    if (e < E) atomicAdd(&g_deg[ei[E + e]], 1);
}

__global__ void k_dinv(int n) {
    int i = blockIdx.x * blockDim.x + threadIdx.x;
    if (i < n) g_dinv[i] = rsqrtf((float)g_deg[i]);
}

__global__ __launch_bounds__(1024) void k_scan1(int n) {
    __shared__ int sh[1024];
    int tid = threadIdx.x;
    int i = blockIdx.x * 1024 + tid;
    int v = (i < n) ? (g_deg[i] - 1) : 0;        // edge count (excl self loop)
    sh[tid] = v;
    __syncthreads();
    for (int o = 1; o < 1024; o <<= 1) {
        int t = (tid >= o) ? sh[tid - o] : 0;
        __syncthreads();
        sh[tid] += t;
        __syncthreads();
    }
    if (i < n) g_off[i] = sh[tid] - v;           // exclusive within block
    if (tid == 1023) g_bsums[blockIdx.x] = sh[1023];
}

__global__ void k_scan2(int nb) {
    __shared__ int sh[256];
    int tid = threadIdx.x;
    int v = (tid < nb) ? g_bsums[tid] : 0;
    sh[tid] = v;
    __syncthreads();
    for (int o = 1; o < 256; o <<= 1) {
        int t = (tid >= o) ? sh[tid - o] : 0;
        __syncthreads();
        sh[tid] += t;
        __syncthreads();
    }
    if (tid < nb) g_bsums[tid] = sh[tid] - v;    // exclusive
}

__global__ void k_scanadd(int n, int E) {
    int i = blockIdx.x * blockDim.x + threadIdx.x;
    if (i < n) g_off[i] += g_bsums[i >> 10];
    if (i == 0) g_off[n] = E;
}

__global__ void k_scatter(const int* __restrict__ ei, int E) {
    int e = blockIdx.x * blockDim.x + threadIdx.x;
    if (e >= E) return;
    int s = ei[e];
    int d = ei[E + e];
    int pos = g_off[d] + atomicAdd(&g_cur[d], 1);
    g_src[pos] = s;
    g_w[pos] = g_dinv[s] * g_dinv[d];
}

// ---------------- packed f32x2 helpers ----------------
__device__ __forceinline__ unsigned long long dup2(float x) {
    unsigned long long r;
    asm("mov.b64 %0, {%1, %1};" : "=l"(r) : "f"(x));
    return r;
}
__device__ __forceinline__ void ffma2(unsigned long long& d,
                                      unsigned long long a, unsigned long long b) {
    asm("fma.rn.f32x2 %0, %1, %2, %0;" : "+l"(d) : "l"(a), "l"(b));
}
__device__ __forceinline__ float2 unpk(unsigned long long v) {
    float2 r;
    asm("mov.b64 {%0, %1}, %2;" : "=f"(r.x), "=f"(r.y) : "l"(v));
    return r;
}

// ---------------- GEMM: g_t[n,64] = A[n,K] @ W[K,64] ----------------
// A == nullptr means read from g_h. 256 threads, tile 128x64,
// thread block 8 rows x 4 cols, packed f32x2 math.
template <int K>
__global__ __launch_bounds__(256) void k_gemm(const float* __restrict__ Ain,
                                              const float* __restrict__ W, int n) {
    const float* A = Ain ? Ain : g_h;
    constexpr int KC = 32;
    constexpr int XLD = 129;                         // bank-conflict-free stride
    __shared__ __align__(16) float Xs[KC * XLD];     // transposed: Xs[k][row]
    __shared__ __align__(16) float Wsh[KC * 64];

    int tid = threadIdx.x;
    int row0 = blockIdx.x * 128;
    int tx = tid & 15, ty = tid >> 4;
    int r0 = ty * 8, c0 = tx * 4;

    unsigned long long acc[8][2];
#pragma unroll
    for (int i = 0; i < 8; i++) { acc[i][0] = 0ull; acc[i][1] = 0ull; }

    for (int kc = 0; kc < K; kc += KC) {
        __syncthreads();
        // load X chunk transposed into shared (coalesced gmem, conflict-free STS)
#pragma unroll
        for (int it = 0; it < 4; ++it) {
            int i = tid + it * 256;          // 0..1023 float4 slots
            int row = i >> 3;                // 0..127
            int k4 = (i & 7) * 4;            // 0..28
            int gr = row0 + row;
            float4 v = make_float4(0.f, 0.f, 0.f, 0.f);
            if (gr < n) v = *(const float4*)&A[(size_t)gr * K + kc + k4];
            Xs[(k4 + 0) * XLD + row] = v.x;
            Xs[(k4 + 1) * XLD + row] = v.y;
            Xs[(k4 + 2) * XLD + row] = v.z;
            Xs[(k4 + 3) * XLD + row] = v.w;
        }
        // load W chunk (contiguous rows of W)
#pragma unroll
        for (int it = 0; it < 2; ++it) {
            int i = tid + it * 256;          // 0..511 float4 slots
            *(float4*)&Wsh[i * 4] = *(const float4*)&W[(size_t)kc * 64 + i * 4];
        }
        __syncthreads();

#pragma unroll
        for (int k = 0; k < KC; ++k) {
            const float* xr = &Xs[k * XLD + r0];
            ulonglong2 w2 = *(const ulonglong2*)&Wsh[k * 64 + c0];
#pragma unroll
            for (int i = 0; i < 8; i++) {
                unsigned long long xd = dup2(xr[i]);
                ffma2(acc[i][0], xd, w2.x);
                ffma2(acc[i][1], xd, w2.y);
            }
        }
    }

#pragma unroll
    for (int i = 0; i < 8; i++) {
        int gr = row0 + r0 + i;
        if (gr < n) {
            float2 a = unpk(acc[i][0]);
            float2 b = unpk(acc[i][1]);
            float4 v = make_float4(a.x, a.y, b.x, b.y);
            *(float4*)&g_t[(size_t)gr * 64 + c0] = v;
        }
    }
}

// ---------------- propagation: out[d] = sum_{e: dst=d} w_e * g_t[src_e]
//                   + dinv[d]^2 * g_t[d] (+bias) (+relu) ----------------
// out == nullptr means write g_h. Warp per node, lane owns 2 features,
// register accumulation, CSR meta via shuffle. No atomics.
__global__ __launch_bounds__(256) void k_prop(float* __restrict__ outp,
                                              const float* __restrict__ bias, int relu,
                                              int n) {
    float* out = outp ? outp : g_h;
    int warp = (blockIdx.x * blockDim.x + threadIdx.x) >> 5;
    int lane = threadIdx.x & 31;
    if (warp >= n) return;
    int node = warp;
    int beg = g_off[node], end = g_off[node + 1];
    const float* tf = g_t + 2 * lane;

    float accx = 0.f, accy = 0.f;
    for (int j = beg; j < end; j += 32) {
        int m = end - j;
        if (m > 32) m = 32;
        int s = 0;
        float wv = 0.f;
        if (lane < m) { s = g_src[j + lane]; wv = g_w[j + lane]; }
#pragma unroll 4
        for (int i = 0; i < m; ++i) {
            int si = __shfl_sync(0xffffffffu, s, i);
            float wi = __shfl_sync(0xffffffffu, wv, i);
            float2 v = *(const float2*)(tf + (size_t)si * 64);
            accx = fmaf(wi, v.x, accx);
            accy = fmaf(wi, v.y, accy);
        }
    }
    // self loop
    float dv = g_dinv[node];
    float2 v0 = *(const float2*)(tf + (size_t)node * 64);
    float w0 = dv * dv;
    accx = fmaf(w0, v0.x, accx);
    accy = fmaf(w0, v0.y, accy);
    if (bias) { accx += bias[2 * lane]; accy += bias[2 * lane + 1]; }
    if (relu) { accx = fmaxf(accx, 0.f); accy = fmaxf(accy, 0.f); }
    *(float2*)(out + (size_t)node * 64 + 2 * lane) = make_float2(accx, accy);
}

// ---------------- launch ----------------
extern "C" void kernel_launch(void* const* d_in, const int* in_sizes, int n_in,
                              void* d_out, int out_size) {
    const float* x     = (const float*)d_in[0];
    const int*   ei    = (const int*)d_in[1];     // int32! (JAX x64 disabled)
    const float* W_in  = (const float*)d_in[2];
    const float* b_in  = (const float*)d_in[3];
    const float* W_h   = (const float*)d_in[4];
    const float* b_h   = (const float*)d_in[5];
    const float* W_out = (const float*)d_in[6];

    int n = in_sizes[0] / 128;
    int E = in_sizes[1] / 2;

    int nb1 = (n + 1023) / 1024;

    // CSR build (fresh every call — deterministic)
    k_init   <<<(n + 255) / 256, 256>>>(n);
    k_count  <<<(E + 255) / 256, 256>>>(ei, E);
    k_dinv   <<<(n + 255) / 256, 256>>>(n);
    k_scan1  <<<nb1, 1024>>>(n);
    k_scan2  <<<1, 256>>>(nb1);
    k_scanadd<<<(n + 255) / 256, 256>>>(n, E);
    k_scatter<<<(E + 255) / 256, 256>>>(ei, E);

    int gb = (n + 127) / 128;
    int pb = (n + 7) / 8;

    // layer 1: h = prop(x @ W_in) + b_in
    k_gemm<128><<<gb, 256>>>(x, W_in, n);
    k_prop<<<pb, 256>>>(nullptr, b_in, 0, n);

    // hidden layers: h = relu(prop(h @ W_h[l]) + b_h[l])
    for (int l = 0; l < 3; ++l) {
        k_gemm<64><<<gb, 256>>>(nullptr, W_h + (size_t)l * 64 * 64, n);
        k_prop<<<pb, 256>>>(nullptr, b_h + (size_t)l * 64, 1, n);
    }

    // output layer: out = prop(h @ W_out), no bias, no relu
    k_gemm<64><<<gb, 256>>>(nullptr, W_out, n);
    k_prop<<<pb, 256>>>((float*)d_out, nullptr, 0, n);
}